// round 1
// baseline (speedup 1.0000x reference)
#include <cuda_runtime.h>
#include <math.h>

#define NSLICE 1088        // 64 * 17 slices per tensor
#define HW     16384       // 128 * 128
#define MAX_DIST 181.02f

// Scratch: distance lookup table (|dy|,|dx|) -> sqrt(dy^2+dx^2), and per-slice d values.
__device__ float g_table[HW];
__device__ float g_d[2 * NSLICE];

// ---------------------------------------------------------------------------
// Kernel 1: build the 128x128 distance table (16K sqrts total, negligible).
// ---------------------------------------------------------------------------
__global__ void build_table_kernel() {
    int i = blockIdx.x * 256 + threadIdx.x;   // grid = 64 * 256 = 16384 exactly
    int dy = i >> 7;
    int dx = i & 127;
    g_table[i] = sqrtf((float)(dy * dy + dx * dx));
}

// ---------------------------------------------------------------------------
// Kernel 2: one block per slice. Pass 1: max + first-argmax. Pass 2: masked
// distance sum via table gather. Writes d (normalized mean distance) to g_d.
// ---------------------------------------------------------------------------
__global__ void __launch_bounds__(256) slice_kernel(const float* __restrict__ a,
                                                    const float* __restrict__ b) {
    const int s = blockIdx.x;                                  // 0 .. 2175
    const float* __restrict__ base =
        (s < NSLICE) ? (a + (size_t)s * HW) : (b + (size_t)(s - NSLICE) * HW);
    const int t = threadIdx.x;
    const int warp = t >> 5, lane = t & 31;

    __shared__ float s_v[8];
    __shared__ int   s_i[8];
    __shared__ float s_s[8];
    __shared__ int   s_c[8];

    // ---------- pass 1: max value + lowest flat index among maxima ----------
    float vmax = -1e30f;
    int   vidx = 0x7fffffff;
    #pragma unroll 8
    for (int k = 0; k < 64; ++k) {
        int e = (k << 8) + t;                 // coalesced: lanes hit consecutive elems
        float v = __ldg(base + e);
        if (v > vmax) { vmax = v; vidx = e; } // in-thread e strictly increases
    }
    #pragma unroll
    for (int off = 16; off > 0; off >>= 1) {
        float ov = __shfl_down_sync(0xffffffffu, vmax, off);
        int   oi = __shfl_down_sync(0xffffffffu, vidx, off);
        if (ov > vmax || (ov == vmax && oi < vidx)) { vmax = ov; vidx = oi; }
    }
    if (lane == 0) { s_v[warp] = vmax; s_i[warp] = vidx; }
    __syncthreads();
    if (t == 0) {
        float bv = s_v[0]; int bi = s_i[0];
        #pragma unroll
        for (int w = 1; w < 8; ++w) {
            if (s_v[w] > bv || (s_v[w] == bv && s_i[w] < bi)) { bv = s_v[w]; bi = s_i[w]; }
        }
        s_v[0] = bv; s_i[0] = bi;
    }
    __syncthreads();
    vmax = s_v[0];
    vidx = s_i[0];

    // ---------- pass 2: masked distance sum (slice should be L2-hot) ----------
    const float thr = vmax * 0.5f;
    const int ym = vidx >> 7;
    const int xm = vidx & 127;

    float sum = 0.0f;
    int   cnt = 0;
    #pragma unroll 8
    for (int k = 0; k < 64; ++k) {
        int e = (k << 8) + t;
        float v = __ldg(base + e);
        if (v > thr) {
            int y = e >> 7, x = e & 127;
            int ady = ::abs(y - ym);
            int adx = ::abs(x - xm);
            sum += __ldg(g_table + (ady << 7) + adx);
            cnt += 1;
        }
    }
    #pragma unroll
    for (int off = 16; off > 0; off >>= 1) {
        sum += __shfl_down_sync(0xffffffffu, sum, off);
        cnt += __shfl_down_sync(0xffffffffu, cnt, off);
    }
    if (lane == 0) { s_s[warp] = sum; s_c[warp] = cnt; }
    __syncthreads();
    if (t == 0) {
        float S = 0.0f; int C = 0;
        #pragma unroll
        for (int w = 0; w < 8; ++w) { S += s_s[w]; C += s_c[w]; }
        float d;
        if (vmax > 0.0f) {
            d = (C > 0) ? (S / (float)C) / MAX_DIST : 1.0f;
        } else {
            d = 0.0f;
        }
        g_d[s] = d;
    }
}

// ---------------------------------------------------------------------------
// Kernel 3: loss = sum |d_a - d_b| / J / B
// ---------------------------------------------------------------------------
__global__ void __launch_bounds__(256) finalize_kernel(float* __restrict__ out) {
    const int t = threadIdx.x;
    float acc = 0.0f;
    for (int i = t; i < NSLICE; i += 256)
        acc += fabsf(g_d[i] - g_d[i + NSLICE]);
    #pragma unroll
    for (int off = 16; off > 0; off >>= 1)
        acc += __shfl_down_sync(0xffffffffu, acc, off);
    __shared__ float sw[8];
    if ((t & 31) == 0) sw[t >> 5] = acc;
    __syncthreads();
    if (t == 0) {
        float S = 0.0f;
        #pragma unroll
        for (int w = 0; w < 8; ++w) S += sw[w];
        out[0] = S / 17.0f / 64.0f;
    }
}

extern "C" void kernel_launch(void* const* d_in, const int* in_sizes, int n_in,
                              void* d_out, int out_size) {
    const float* a = (const float*)d_in[0];   // output heatmaps [64,17,128,128] f32
    const float* b = (const float*)d_in[1];   // target heatmaps [64,17,128,128] f32
    (void)in_sizes; (void)n_in; (void)out_size;

    build_table_kernel<<<64, 256>>>();
    slice_kernel<<<2 * NSLICE, 256>>>(a, b);
    finalize_kernel<<<1, 256>>>((float*)d_out);
}

// round 2
// speedup vs baseline: 1.0856x; 1.0856x over previous
#include <cuda_runtime.h>
#include <math.h>

#define NSLICE 1088        // 64 * 17 slices per tensor
#define HW     16384       // 128 * 128
#define MAX_DIST 181.02f

__device__ float g_table[HW];      // (|dy|,|dx|) -> sqrt(dy^2+dx^2)
__device__ float g_d[2 * NSLICE];  // per-slice normalized mean distance

// ---------------------------------------------------------------------------
// Kernel 1: build the 128x128 distance table (16K sqrts, ~1-2us).
// ---------------------------------------------------------------------------
__global__ void build_table_kernel() {
    int i = blockIdx.x * 256 + threadIdx.x;   // grid = 64 * 256 = 16384 exactly
    int dy = i >> 7;
    int dx = i & 127;
    g_table[i] = sqrtf((float)(dy * dy + dx * dx));
}

// ---------------------------------------------------------------------------
// Kernel 2: one block per slice. Pass 1: vectorized DRAM load -> smem cache +
// (max, first-argmax). Pass 2: masked distance sum reading smem + L1-resident
// table. Writes normalized mean distance to g_d.
// ---------------------------------------------------------------------------
__global__ void __launch_bounds__(256) slice_kernel(const float* __restrict__ a,
                                                    const float* __restrict__ b) {
    extern __shared__ float4 sv[];             // 4096 float4 = 64 KB slice cache
    const int s = blockIdx.x;                  // 0 .. 2175
    const float4* __restrict__ base = (const float4*)(
        (s < NSLICE) ? (a + (size_t)s * HW) : (b + (size_t)(s - NSLICE) * HW));
    const int t = threadIdx.x;
    const int warp = t >> 5, lane = t & 31;

    __shared__ float s_v[8];
    __shared__ int   s_i[8];
    __shared__ float s_s[8];
    __shared__ int   s_c[8];

    // ---------- pass 1: stream slice to smem, track max + lowest flat idx ----
    float vmax = -1e30f;
    int   vidx = 0x7fffffff;
    #pragma unroll
    for (int k = 0; k < 16; ++k) {
        int q = (k << 8) + t;                  // float4 index, coalesced
        float4 v = __ldg(base + q);
        sv[q] = v;
        int e = q << 2;                        // flat element index of v.x
        if (v.x > vmax) { vmax = v.x; vidx = e; }
        if (v.y > vmax) { vmax = v.y; vidx = e + 1; }
        if (v.z > vmax) { vmax = v.z; vidx = e + 2; }
        if (v.w > vmax) { vmax = v.w; vidx = e + 3; }
    }
    #pragma unroll
    for (int off = 16; off > 0; off >>= 1) {
        float ov = __shfl_down_sync(0xffffffffu, vmax, off);
        int   oi = __shfl_down_sync(0xffffffffu, vidx, off);
        if (ov > vmax || (ov == vmax && oi < vidx)) { vmax = ov; vidx = oi; }
    }
    if (lane == 0) { s_v[warp] = vmax; s_i[warp] = vidx; }
    __syncthreads();                           // also orders STS before pass-2 LDS
    {   // every thread reduces the 8 warp results (avoids a second barrier)
        float bv = s_v[0]; int bi = s_i[0];
        #pragma unroll
        for (int w = 1; w < 8; ++w) {
            float wv = s_v[w]; int wi = s_i[w];
            if (wv > bv || (wv == bv && wi < bi)) { bv = wv; bi = wi; }
        }
        vmax = bv; vidx = bi;
    }

    // ---------- pass 2: masked distance sum from smem ------------------------
    const float thr = vmax * 0.5f;
    const int ym = vidx >> 7;
    const int xm = vidx & 127;

    float sum = 0.0f;
    int   cnt = 0;
    #pragma unroll
    for (int k = 0; k < 16; ++k) {
        int q = (k << 8) + t;
        float4 v = sv[q];
        int e = q << 2;
        int y = e >> 7;                        // all 4 components share the row
        int ady = ::abs(y - ym);
        const float* __restrict__ row = g_table + (ady << 7);
        int x0 = e & 127;
        if (v.x > thr) { sum += __ldg(row + ::abs(x0     - xm)); ++cnt; }
        if (v.y > thr) { sum += __ldg(row + ::abs(x0 + 1 - xm)); ++cnt; }
        if (v.z > thr) { sum += __ldg(row + ::abs(x0 + 2 - xm)); ++cnt; }
        if (v.w > thr) { sum += __ldg(row + ::abs(x0 + 3 - xm)); ++cnt; }
    }
    #pragma unroll
    for (int off = 16; off > 0; off >>= 1) {
        sum += __shfl_down_sync(0xffffffffu, sum, off);
        cnt += __shfl_down_sync(0xffffffffu, cnt, off);
    }
    if (lane == 0) { s_s[warp] = sum; s_c[warp] = cnt; }
    __syncthreads();
    if (t == 0) {
        float S = 0.0f; int C = 0;
        #pragma unroll
        for (int w = 0; w < 8; ++w) { S += s_s[w]; C += s_c[w]; }
        float d;
        if (vmax > 0.0f) {
            d = (C > 0) ? (S / (float)C) / MAX_DIST : 1.0f;
        } else {
            d = 0.0f;
        }
        g_d[s] = d;
    }
}

// ---------------------------------------------------------------------------
// Kernel 3: loss = sum |d_a - d_b| / J / B
// ---------------------------------------------------------------------------
__global__ void __launch_bounds__(256) finalize_kernel(float* __restrict__ out) {
    const int t = threadIdx.x;
    float acc = 0.0f;
    for (int i = t; i < NSLICE; i += 256)
        acc += fabsf(g_d[i] - g_d[i + NSLICE]);
    #pragma unroll
    for (int off = 16; off > 0; off >>= 1)
        acc += __shfl_down_sync(0xffffffffu, acc, off);
    __shared__ float sw[8];
    if ((t & 31) == 0) sw[t >> 5] = acc;
    __syncthreads();
    if (t == 0) {
        float S = 0.0f;
        #pragma unroll
        for (int w = 0; w < 8; ++w) S += sw[w];
        out[0] = S / 17.0f / 64.0f;
    }
}

extern "C" void kernel_launch(void* const* d_in, const int* in_sizes, int n_in,
                              void* d_out, int out_size) {
    const float* a = (const float*)d_in[0];   // output heatmaps [64,17,128,128] f32
    const float* b = (const float*)d_in[1];   // target heatmaps [64,17,128,128] f32
    (void)in_sizes; (void)n_in; (void)out_size;

    static bool attr_set = false;
    if (!attr_set) {   // host-side attribute, not a stream op; safe under capture
        cudaFuncSetAttribute(slice_kernel,
                             cudaFuncAttributeMaxDynamicSharedMemorySize, 65536);
        attr_set = true;
    }

    build_table_kernel<<<64, 256>>>();
    slice_kernel<<<2 * NSLICE, 256, 65536>>>(a, b);
    finalize_kernel<<<1, 256>>>((float*)d_out);
}

// round 3
// speedup vs baseline: 1.0914x; 1.0054x over previous
#include <cuda_runtime.h>
#include <math.h>
#include <stdint.h>

#define NSLICE 1088        // 64 * 17 slices per tensor
#define HW     16384       // 128 * 128
#define SLICE_BYTES 65536
#define MAX_DIST 181.02f
#define NCTA 148
#define NTH  512

__device__ float g_table[HW];      // (|dy|,|dx|) -> sqrt(dy^2+dx^2)
__device__ float g_d[2 * NSLICE];  // per-slice normalized mean distance

// ---------------------------------------------------------------------------
// Kernel 1: build the 128x128 distance table in global memory.
// ---------------------------------------------------------------------------
__global__ void build_table_kernel() {
    int i = blockIdx.x * 256 + threadIdx.x;   // grid = 64 * 256 = 16384
    int dy = i >> 7;
    int dx = i & 127;
    g_table[i] = sqrtf((float)(dy * dy + dx * dx));
}

// ---------------------------------------------------------------------------
// mbarrier / bulk-copy helpers
// ---------------------------------------------------------------------------
__device__ __forceinline__ uint32_t smem_u32(const void* p) {
    return (uint32_t)__cvta_generic_to_shared(p);
}
__device__ __forceinline__ void mbar_init(uint32_t a, uint32_t cnt) {
    asm volatile("mbarrier.init.shared::cta.b64 [%0], %1;" :: "r"(a), "r"(cnt) : "memory");
}
__device__ __forceinline__ void mbar_arrive_expect(uint32_t a, uint32_t bytes) {
    asm volatile("mbarrier.arrive.expect_tx.shared::cta.b64 _, [%0], %1;"
                 :: "r"(a), "r"(bytes) : "memory");
}
__device__ __forceinline__ void bulk_g2s(uint32_t dst, const void* src,
                                         uint32_t bytes, uint32_t mbar) {
    asm volatile("cp.async.bulk.shared::cta.global.mbarrier::complete_tx::bytes "
                 "[%0], [%1], %2, [%3];"
                 :: "r"(dst), "l"(src), "r"(bytes), "r"(mbar) : "memory");
}
__device__ __forceinline__ void mbar_wait(uint32_t a, uint32_t parity) {
    asm volatile(
        "{\n\t.reg .pred P;\n\t"
        "WAIT_%=:\n\t"
        "mbarrier.try_wait.parity.shared::cta.b64 P, [%0], %1;\n\t"
        "@!P bra WAIT_%=;\n\t}"
        :: "r"(a), "r"(parity) : "memory");
}

// ---------------------------------------------------------------------------
// Kernel 2: persistent CTAs (1/SM). Double-buffered cp.async.bulk pipeline,
// f32 distance table in smem, pass-1 values held in registers for pass 2.
// ---------------------------------------------------------------------------
__global__ void __launch_bounds__(NTH, 1) slice_kernel(const float* __restrict__ a,
                                                       const float* __restrict__ b) {
    extern __shared__ float smem[];
    float* buf[2] = { smem, smem + HW };
    float* tab = smem + 2 * HW;

    __shared__ __align__(8) unsigned long long mbar_store[2];
    __shared__ float s_v[16];
    __shared__ int   s_i[16];
    __shared__ float s_s[16];
    __shared__ int   s_c[16];

    const int t = threadIdx.x;
    const int warp = t >> 5, lane = t & 31;
    const int cta = blockIdx.x;
    const int total = 2 * NSLICE;
    const int n = (total - cta + NCTA - 1) / NCTA;   // 14 or 15 slices

    const uint32_t mb[2] = { smem_u32(&mbar_store[0]), smem_u32(&mbar_store[1]) };

    if (t == 0) { mbar_init(mb[0], 1); mbar_init(mb[1], 1); }
    __syncthreads();

    // Issue the first two slice loads, then copy the table into smem.
    if (t == 0) {
        {
            int s = cta;   // slice 0 of this CTA (n >= 14 always)
            const float* p = (s < NSLICE) ? (a + (size_t)s * HW)
                                          : (b + (size_t)(s - NSLICE) * HW);
            mbar_arrive_expect(mb[0], SLICE_BYTES);
            bulk_g2s(smem_u32(buf[0]), p, SLICE_BYTES, mb[0]);
        }
        {
            int s = cta + NCTA;
            const float* p = (s < NSLICE) ? (a + (size_t)s * HW)
                                          : (b + (size_t)(s - NSLICE) * HW);
            mbar_arrive_expect(mb[1], SLICE_BYTES);
            bulk_g2s(smem_u32(buf[1]), p, SLICE_BYTES, mb[1]);
        }
    }
    {   // table -> smem (readers are separated by the pass-1 reduction barrier)
        const float4* gt = (const float4*)g_table;
        float4* st = (float4*)tab;
        #pragma unroll
        for (int k = 0; k < 8; ++k) st[k * NTH + t] = __ldg(gt + k * NTH + t);
    }

    for (int i = 0; i < n; ++i) {
        const int bsel = i & 1;
        mbar_wait(mb[bsel], (i >> 1) & 1);

        // ---------- pass 1: smem -> regs, max + lowest flat index ----------
        const float4* bf4 = (const float4*)buf[bsel];
        float4 v[8];
        float vmax = -1e30f;
        int   vidx = 0x7fffffff;
        #pragma unroll
        for (int k = 0; k < 8; ++k) {
            v[k] = bf4[k * NTH + t];
            int e = (k * NTH + t) << 2;       // strictly increasing in-thread
            if (v[k].x > vmax) { vmax = v[k].x; vidx = e; }
            if (v[k].y > vmax) { vmax = v[k].y; vidx = e + 1; }
            if (v[k].z > vmax) { vmax = v[k].z; vidx = e + 2; }
            if (v[k].w > vmax) { vmax = v[k].w; vidx = e + 3; }
        }
        #pragma unroll
        for (int off = 16; off > 0; off >>= 1) {
            float ov = __shfl_down_sync(0xffffffffu, vmax, off);
            int   oi = __shfl_down_sync(0xffffffffu, vidx, off);
            if (ov > vmax || (ov == vmax && oi < vidx)) { vmax = ov; vidx = oi; }
        }
        if (lane == 0) { s_v[warp] = vmax; s_i[warp] = vidx; }
        __syncthreads();   // buffer fully consumed (values live in regs)

        // prefetch slice i+2 into the freed buffer, overlapping pass 2
        if (t == 0 && i + 2 < n) {
            int s = cta + (i + 2) * NCTA;
            const float* p = (s < NSLICE) ? (a + (size_t)s * HW)
                                          : (b + (size_t)(s - NSLICE) * HW);
            mbar_arrive_expect(mb[bsel], SLICE_BYTES);
            bulk_g2s(smem_u32(buf[bsel]), p, SLICE_BYTES, mb[bsel]);
        }

        // every thread reduces the 16 warp results
        float bv = s_v[0]; int bi = s_i[0];
        #pragma unroll
        for (int w = 1; w < 16; ++w) {
            float wv = s_v[w]; int wi = s_i[w];
            if (wv > bv || (wv == bv && wi < bi)) { bv = wv; bi = wi; }
        }

        // ---------- pass 2: masked distance sum (regs + smem table) ----------
        const float thr = bv * 0.5f;
        const int ym = bi >> 7;
        const int xm = bi & 127;
        float sum = 0.0f;
        int   cnt = 0;
        #pragma unroll
        for (int k = 0; k < 8; ++k) {
            int e = (k * NTH + t) << 2;
            int y = e >> 7;                    // 4 components share the row
            const float* row = tab + (::abs(y - ym) << 7);
            int x0 = e & 127;
            if (v[k].x > thr) { sum += row[::abs(x0     - xm)]; ++cnt; }
            if (v[k].y > thr) { sum += row[::abs(x0 + 1 - xm)]; ++cnt; }
            if (v[k].z > thr) { sum += row[::abs(x0 + 2 - xm)]; ++cnt; }
            if (v[k].w > thr) { sum += row[::abs(x0 + 3 - xm)]; ++cnt; }
        }
        #pragma unroll
        for (int off = 16; off > 0; off >>= 1) {
            sum += __shfl_down_sync(0xffffffffu, sum, off);
            cnt += __shfl_down_sync(0xffffffffu, cnt, off);
        }
        if (lane == 0) { s_s[warp] = sum; s_c[warp] = cnt; }
        __syncthreads();
        if (t == 0) {
            float S = 0.0f; int C = 0;
            #pragma unroll
            for (int w = 0; w < 16; ++w) { S += s_s[w]; C += s_c[w]; }
            float d;
            if (bv > 0.0f) {
                d = (C > 0) ? (S / (float)C) / MAX_DIST : 1.0f;
            } else {
                d = 0.0f;
            }
            g_d[cta + i * NCTA] = d;
        }
        __syncthreads();   // s_v/s_s reused next iteration
    }
}

// ---------------------------------------------------------------------------
// Kernel 3: loss = sum |d_a - d_b| / J / B
// ---------------------------------------------------------------------------
__global__ void __launch_bounds__(256) finalize_kernel(float* __restrict__ out) {
    const int t = threadIdx.x;
    float acc = 0.0f;
    for (int i = t; i < NSLICE; i += 256)
        acc += fabsf(g_d[i] - g_d[i + NSLICE]);
    #pragma unroll
    for (int off = 16; off > 0; off >>= 1)
        acc += __shfl_down_sync(0xffffffffu, acc, off);
    __shared__ float sw[8];
    if ((t & 31) == 0) sw[t >> 5] = acc;
    __syncthreads();
    if (t == 0) {
        float S = 0.0f;
        #pragma unroll
        for (int w = 0; w < 8; ++w) S += sw[w];
        out[0] = S / 17.0f / 64.0f;
    }
}

extern "C" void kernel_launch(void* const* d_in, const int* in_sizes, int n_in,
                              void* d_out, int out_size) {
    const float* a = (const float*)d_in[0];   // output heatmaps [64,17,128,128] f32
    const float* b = (const float*)d_in[1];   // target heatmaps [64,17,128,128] f32
    (void)in_sizes; (void)n_in; (void)out_size;

    static bool attr_set = false;
    if (!attr_set) {
        cudaFuncSetAttribute(slice_kernel,
                             cudaFuncAttributeMaxDynamicSharedMemorySize, 3 * HW * 4);
        attr_set = true;
    }

    build_table_kernel<<<64, 256>>>();
    slice_kernel<<<NCTA, NTH, 3 * HW * 4>>>(a, b);
    finalize_kernel<<<1, 256>>>((float*)d_out);
}